// round 15
// baseline (speedup 1.0000x reference)
#include <cuda_runtime.h>
#include <cuda_bf16.h>
#include <math.h>
#include <cstdint>

// Problem constants
#define BB 2
#define SS 2048
#define HID 2048
#define NH 32
#define NKV 4
#define DD 64
#define N_REP 8
#define MROWS (BB * SS)           // 4096
#define QSCALE 0.125f             // D^-0.5
#define EPS 1e-6f

// fused projection layout: [Wq(2048) ; Wk(256) ; Wv(256) ; Wg(2048)]
#define NQKVG 4608
#define COL_Q 0
#define COL_K 2048
#define COL_V 2304
#define COL_G 2560

// ---------------- async copy helpers ----------------------------------------
#define CP_ASYNC16(smem_u32a, gptr) \
    asm volatile("cp.async.cg.shared.global [%0], [%1], 16;" :: "r"(smem_u32a), "l"(gptr))
#define CP_COMMIT() asm volatile("cp.async.commit_group;" ::: "memory")
#define CP_WAIT1()  asm volatile("cp.async.wait_group 1;" ::: "memory")
#define CP_WAIT0()  asm volatile("cp.async.wait_group 0;" ::: "memory")

__device__ __forceinline__ uint32_t smem_u32(const void* p) {
    uint32_t a;
    asm("{ .reg .u64 t; cvta.to.shared.u64 t, %1; cvt.u32.u64 %0, t; }" : "=r"(a) : "l"(p));
    return a;
}
__device__ __forceinline__ void ldsm_x4(uint32_t& r0, uint32_t& r1, uint32_t& r2, uint32_t& r3,
                                        uint32_t addr) {
    asm volatile("ldmatrix.sync.aligned.m8n8.x4.shared.b16 {%0,%1,%2,%3}, [%4];"
                 : "=r"(r0), "=r"(r1), "=r"(r2), "=r"(r3) : "r"(addr));
}
__device__ __forceinline__ void mma16816(float& c0, float& c1, float& c2, float& c3,
                                         uint32_t a0, uint32_t a1, uint32_t a2, uint32_t a3,
                                         uint32_t b0, uint32_t b1) {
    asm volatile(
        "mma.sync.aligned.m16n8k16.row.col.f32.bf16.bf16.f32 "
        "{%0,%1,%2,%3}, {%4,%5,%6,%7}, {%8,%9}, {%0,%1,%2,%3};"
        : "+f"(c0), "+f"(c1), "+f"(c2), "+f"(c3)
        : "r"(a0), "r"(a1), "r"(a2), "r"(a3), "r"(b0), "r"(b1));
}
__device__ __forceinline__ uint32_t pack_bf162(float x, float y) {
    __nv_bfloat162 h = __floats2bfloat162_rn(x, y);
    return *reinterpret_cast<uint32_t*>(&h);
}

// ---------------- scratch (static device memory) ----------------------------
__device__ float d_qkvg[(size_t)MROWS * NQKVG];   // fused projection output

__device__ __nv_bfloat16 g_hs_h[(size_t)MROWS * HID];
__device__ __nv_bfloat16 g_hs_l[(size_t)MROWS * HID];
__device__ __nv_bfloat16 g_wqkvg_h[(size_t)NQKVG * HID];
__device__ __nv_bfloat16 g_wqkvg_l[(size_t)NQKVG * HID];
__device__ __nv_bfloat16 g_wo_h[(size_t)HID * HID];
__device__ __nv_bfloat16 g_wo_l[(size_t)HID * HID];
__device__ __nv_bfloat16 g_ab_h[(size_t)MROWS * HID];
__device__ __nv_bfloat16 g_ab_l[(size_t)MROWS * HID];

// pre-split attention operands (bf16 hi/lo)
__device__ __nv_bfloat16 g_qh[(size_t)MROWS * NH * DD];
__device__ __nv_bfloat16 g_ql[(size_t)MROWS * NH * DD];
__device__ __nv_bfloat16 g_kh[(size_t)MROWS * NKV * DD];
__device__ __nv_bfloat16 g_kl[(size_t)MROWS * NKV * DD];
__device__ __nv_bfloat16 g_vth[(size_t)MROWS * NKV * DD];  // [b][kvh][d][s]
__device__ __nv_bfloat16 g_vtl[(size_t)MROWS * NKV * DD];

// ---------------- split fp32 -> bf16 hi/lo ----------------------------------
__global__ __launch_bounds__(256) void split_bf16(
    const float* __restrict__ X, __nv_bfloat16* __restrict__ hi,
    __nv_bfloat16* __restrict__ lo, int n4)
{
    int i = blockIdx.x * 256 + threadIdx.x;
    if (i >= n4) return;
    float4 x = ((const float4*)X)[i];
    __nv_bfloat16 h0 = __float2bfloat16(x.x);
    __nv_bfloat16 h1 = __float2bfloat16(x.y);
    __nv_bfloat16 h2 = __float2bfloat16(x.z);
    __nv_bfloat16 h3 = __float2bfloat16(x.w);
    __nv_bfloat16 l0 = __float2bfloat16(x.x - __bfloat162float(h0));
    __nv_bfloat16 l1 = __float2bfloat16(x.y - __bfloat162float(h1));
    __nv_bfloat16 l2 = __float2bfloat16(x.z - __bfloat162float(h2));
    __nv_bfloat16 l3 = __float2bfloat16(x.w - __bfloat162float(h3));
    ((__nv_bfloat162*)hi)[2*i]     = __nv_bfloat162(h0, h1);
    ((__nv_bfloat162*)hi)[2*i + 1] = __nv_bfloat162(h2, h3);
    ((__nv_bfloat162*)lo)[2*i]     = __nv_bfloat162(l0, l1);
    ((__nv_bfloat162*)lo)[2*i + 1] = __nv_bfloat162(l2, l3);
}

// ---------------- HMMA bf16x3 GEMM: BK=32, 2-stage, 2 CTAs/SM ----------------
// C[m,n] = sum_k (AhBh + AhBl + AlBh). CTA 128x128, 8 warps 32x64.
// Stage: 4 tiles of 128x32 bf16, pitch 40 elems (80 B) -> conflict-free ldsm.
#define GP32 40
#define G32_TILE (128 * GP32 * 2)   // 10240 per tile
#define G32_STAGE (4 * G32_TILE)    // 40960 per stage
#define GEMM_SMEM (2 * G32_STAGE)   // 81920 -> 2 CTAs/SM

__global__ __launch_bounds__(256, 2) void gemm_bf16x3(
    const __nv_bfloat16* __restrict__ Ah, const __nv_bfloat16* __restrict__ Al,
    const __nv_bfloat16* __restrict__ Bh, const __nv_bfloat16* __restrict__ Bl,
    float* __restrict__ C, int M, int N, int K)
{
    extern __shared__ char smem[];
    const uint32_t sbase = smem_u32(smem);
    const int tid = threadIdx.x;
    const int wid = tid >> 5;
    const int lane = tid & 31;
    const int wm = wid & 3;
    const int wn = wid >> 2;
    const int bm = blockIdx.y * 128;
    const int bn = blockIdx.x * 128;

    const int nchunk = K >> 5;          // BK=32
    const int lrow = tid >> 2;          // 0..63
    const int lcol = (tid & 3) * 8;     // bf16 col (4 x 16B chunks per 64B row)

    const int g = lane >> 3, li = lane & 7;
    const int a_row = (g & 1) * 8 + li;
    const int a_kof = (g >> 1) * 8;
    const int b_nof = (g >> 1) * 8 + li;
    const int b_kof = (g & 1) * 8;

    float acc[2][8][4];
#pragma unroll
    for (int mt = 0; mt < 2; mt++)
#pragma unroll
        for (int nt = 0; nt < 8; nt++)
#pragma unroll
            for (int r = 0; r < 4; r++) acc[mt][nt][r] = 0.f;

    auto load_stage = [&](int s, int k0) {
        const uint32_t st = sbase + s * G32_STAGE;
#pragma unroll
        for (int u = 0; u < 2; u++) {
            int row = lrow + u * 64;
            uint32_t so = (uint32_t)(row * GP32 + lcol) * 2;
            const size_t ga = (size_t)(bm + row) * K + k0 + lcol;
            const size_t gb = (size_t)(bn + row) * K + k0 + lcol;
            CP_ASYNC16(st + so,                Ah + ga);
            CP_ASYNC16(st + G32_TILE + so,     Al + ga);
            CP_ASYNC16(st + 2 * G32_TILE + so, Bh + gb);
            CP_ASYNC16(st + 3 * G32_TILE + so, Bl + gb);
        }
        CP_COMMIT();
    };

    load_stage(0, 0);

    for (int i = 0; i < nchunk; i++) {
        const int s = i & 1;
        if (i + 1 < nchunk) { load_stage(s ^ 1, (i + 1) << 5); CP_WAIT1(); }
        else                { CP_WAIT0(); }
        __syncthreads();

        const uint32_t st = sbase + s * G32_STAGE;
        const uint32_t aBase = st + (uint32_t)((wm * 32 + a_row) * GP32 + a_kof) * 2;
        const uint32_t bBase = st + 2 * G32_TILE + (uint32_t)((wn * 64 + b_nof) * GP32 + b_kof) * 2;

#pragma unroll
        for (int ks = 0; ks < 2; ks++) {
            const uint32_t ko = ks * 32;   // 16 bf16 = 32 B per k-step
            uint32_t ah0[4], ah1[4], al0[4], al1[4];
            ldsm_x4(ah0[0], ah0[1], ah0[2], ah0[3], aBase + ko);
            ldsm_x4(ah1[0], ah1[1], ah1[2], ah1[3], aBase + (uint32_t)(16 * GP32) * 2 + ko);
            ldsm_x4(al0[0], al0[1], al0[2], al0[3], aBase + G32_TILE + ko);
            ldsm_x4(al1[0], al1[1], al1[2], al1[3], aBase + G32_TILE + (uint32_t)(16 * GP32) * 2 + ko);

            uint32_t bf[4][4];
#pragma unroll
            for (int p = 0; p < 4; p++)
                ldsm_x4(bf[p][0], bf[p][1], bf[p][2], bf[p][3],
                        bBase + (uint32_t)(p * 16 * GP32) * 2 + ko);
#pragma unroll
            for (int nt = 0; nt < 8; nt++) {
                const int p = nt >> 1, h = nt & 1;
                uint32_t b0 = bf[p][h * 2], b1 = bf[p][h * 2 + 1];
                mma16816(acc[0][nt][0], acc[0][nt][1], acc[0][nt][2], acc[0][nt][3],
                         ah0[0], ah0[1], ah0[2], ah0[3], b0, b1);
                mma16816(acc[1][nt][0], acc[1][nt][1], acc[1][nt][2], acc[1][nt][3],
                         ah1[0], ah1[1], ah1[2], ah1[3], b0, b1);
                mma16816(acc[0][nt][0], acc[0][nt][1], acc[0][nt][2], acc[0][nt][3],
                         al0[0], al0[1], al0[2], al0[3], b0, b1);
                mma16816(acc[1][nt][0], acc[1][nt][1], acc[1][nt][2], acc[1][nt][3],
                         al1[0], al1[1], al1[2], al1[3], b0, b1);
            }
#pragma unroll
            for (int p = 0; p < 4; p++)
                ldsm_x4(bf[p][0], bf[p][1], bf[p][2], bf[p][3],
                        bBase + G32_TILE + (uint32_t)(p * 16 * GP32) * 2 + ko);
#pragma unroll
            for (int nt = 0; nt < 8; nt++) {
                const int p = nt >> 1, h = nt & 1;
                uint32_t b0 = bf[p][h * 2], b1 = bf[p][h * 2 + 1];
                mma16816(acc[0][nt][0], acc[0][nt][1], acc[0][nt][2], acc[0][nt][3],
                         ah0[0], ah0[1], ah0[2], ah0[3], b0, b1);
                mma16816(acc[1][nt][0], acc[1][nt][1], acc[1][nt][2], acc[1][nt][3],
                         ah1[0], ah1[1], ah1[2], ah1[3], b0, b1);
            }
        }
        __syncthreads();
    }

    const int crow = lane >> 2;
    const int ccol = (lane & 3) * 2;
#pragma unroll
    for (int mt = 0; mt < 2; mt++) {
        int m0 = bm + wm * 32 + mt * 16 + crow;
#pragma unroll
        for (int nt = 0; nt < 8; nt++) {
            int n0 = bn + wn * 64 + nt * 8 + ccol;
            *(float2*)(C + (size_t)m0 * N + n0)       = make_float2(acc[mt][nt][0], acc[mt][nt][1]);
            *(float2*)(C + (size_t)(m0 + 8) * N + n0) = make_float2(acc[mt][nt][2], acc[mt][nt][3]);
        }
    }
}

// ---------------- RMSNorm + RoPE + bf16 hi/lo split (strided input) ----------
__global__ __launch_bounds__(256) void norm_rope_split(
    const float* __restrict__ X, const float* __restrict__ cosb,
    const float* __restrict__ sinb, const float* __restrict__ gamma,
    __nv_bfloat16* __restrict__ Xh, __nv_bfloat16* __restrict__ Xl,
    int nheads, int total_rows, float scale, int rowstride, int colbase)
{
    int warp = (blockIdx.x * 256 + threadIdx.x) >> 5;
    int lane = threadIdx.x & 31;
    if (warp >= total_rows) return;
    int bs = warp / nheads;
    int h  = warp - bs * nheads;
    const float* x = X + (size_t)bs * rowstride + colbase + h * DD;
    float v0 = x[lane];
    float v1 = x[lane + 32];
    float ss = v0 * v0 + v1 * v1;
#pragma unroll
    for (int o = 16; o > 0; o >>= 1) ss += __shfl_xor_sync(0xffffffffu, ss, o);
    float inv = rsqrtf(ss * (1.0f / DD) + EPS);
    float n0 = v0 * inv * gamma[lane];
    float n1 = v1 * inv * gamma[lane + 32];
    const float* cp = cosb + (size_t)bs * DD;
    const float* sp = sinb + (size_t)bs * DD;
    float r0 = (n0 * cp[lane]      - n1 * sp[lane])      * scale;
    float r1 = (n1 * cp[lane + 32] + n0 * sp[lane + 32]) * scale;
    __nv_bfloat16 h0 = __float2bfloat16(r0);
    __nv_bfloat16 h1 = __float2bfloat16(r1);
    Xh[(size_t)warp * DD + lane]      = h0;
    Xh[(size_t)warp * DD + lane + 32] = h1;
    Xl[(size_t)warp * DD + lane]      = __float2bfloat16(r0 - __bfloat162float(h0));
    Xl[(size_t)warp * DD + lane + 32] = __float2bfloat16(r1 - __bfloat162float(h1));
}

// ---------------- V: fp32 strided -> bf16 hi/lo transposed [b,kvh,d,s] -------
__global__ __launch_bounds__(256) void split_v_trans(
    const float* __restrict__ QKVG, __nv_bfloat16* __restrict__ Vth,
    __nv_bfloat16* __restrict__ Vtl)
{
    __shared__ float tile[64][65];
    const int sb = blockIdx.x * 64;
    const int kvh = blockIdx.y;
    const int b = blockIdx.z;
    const int tid = threadIdx.x;
#pragma unroll
    for (int i = tid; i < 1024; i += 256) {
        int r = i >> 4;
        int c4 = (i & 15) << 2;
        float4 v = *(const float4*)(QKVG + (size_t)(b * SS + sb + r) * NQKVG + COL_V + kvh * DD + c4);
        tile[r][c4 + 0] = v.x; tile[r][c4 + 1] = v.y;
        tile[r][c4 + 2] = v.z; tile[r][c4 + 3] = v.w;
    }
    __syncthreads();
#pragma unroll
    for (int i = tid; i < 1024; i += 256) {
        int d = i >> 4;
        int s4 = (i & 15) << 2;
        size_t base = ((size_t)(b * NKV + kvh) * DD + d) * SS + sb + s4;
        __nv_bfloat16 hs4[4], ls4[4];
#pragma unroll
        for (int j = 0; j < 4; j++) {
            float v = tile[s4 + j][d];
            hs4[j] = __float2bfloat16(v);
            ls4[j] = __float2bfloat16(v - __bfloat162float(hs4[j]));
        }
        *(__nv_bfloat162*)(Vth + base)     = __nv_bfloat162(hs4[0], hs4[1]);
        *(__nv_bfloat162*)(Vth + base + 2) = __nv_bfloat162(hs4[2], hs4[3]);
        *(__nv_bfloat162*)(Vtl + base)     = __nv_bfloat162(ls4[0], ls4[1]);
        *(__nv_bfloat162*)(Vtl + base + 2) = __nv_bfloat162(ls4[2], ls4[3]);
    }
}

// ---------------- HMMA flash attention, cp.async pipelined -------------------
#define AT_PITCH 144
#define AT_TILE (64 * AT_PITCH)       // 9216
#define AT_STAGE (4 * AT_TILE)        // 36864
#define ATT_SMEM (2 * AT_STAGE)       // 73728

__global__ __launch_bounds__(256) void attn_hmma()
{
    extern __shared__ char sm8[];
    const uint32_t sbase = smem_u32(sm8);
    const int qt = blockIdx.x;
    const int h  = blockIdx.y;
    const int b  = blockIdx.z;
    const int kvh = h >> 3;
    const int tid = threadIdx.x;
    const int wid = tid >> 5;
    const int lane = tid & 31;
    const int g = lane >> 3, li = lane & 7;
    const int a_row = (g & 1) * 8 + li;
    const int a_kof = (g >> 1) * 8;
    const int b_nof = (g >> 1) * 8 + li;
    const int b_kof = (g & 1) * 8;
    const int lr = tid >> 3;
    const int lc = tid & 7;

    // ---- group A: Q hi/lo into stage-1 area
    {
        const __nv_bfloat16* Qh = g_qh + ((size_t)(b * SS + qt * 128) * NH + h) * DD;
        const __nv_bfloat16* Ql = g_ql + ((size_t)(b * SS + qt * 128) * NH + h) * DD;
#pragma unroll
        for (int u = 0; u < 4; u++) {
            int r = u * 32 + lr;
            uint32_t dof = (uint32_t)r * AT_PITCH + lc * 16;
            CP_ASYNC16(sbase + AT_STAGE + dof,         Qh + (size_t)r * (NH * DD) + lc * 8);
            CP_ASYNC16(sbase + AT_STAGE + 18432 + dof, Ql + (size_t)r * (NH * DD) + lc * 8);
        }
        CP_COMMIT();
    }

    auto load_kv = [&](int s, int kt) {
        const __nv_bfloat16* Kh = g_kh + ((size_t)(b * SS + kt * 64) * NKV + kvh) * DD;
        const __nv_bfloat16* Kl = g_kl + ((size_t)(b * SS + kt * 64) * NKV + kvh) * DD;
        const __nv_bfloat16* Vh = g_vth + (size_t)(b * NKV + kvh) * DD * SS + kt * 64;
        const __nv_bfloat16* Vl = g_vtl + (size_t)(b * NKV + kvh) * DD * SS + kt * 64;
        const uint32_t sb0 = sbase + s * AT_STAGE;
#pragma unroll
        for (int u = 0; u < 8; u++) {
            const int t = u >> 1;
            const int r = (u & 1) * 32 + lr;
            uint32_t dst = sb0 + t * AT_TILE + (uint32_t)r * AT_PITCH + lc * 16;
            const __nv_bfloat16* src;
            if      (t == 0) src = Kh + (size_t)r * (NKV * DD) + lc * 8;
            else if (t == 1) src = Kl + (size_t)r * (NKV * DD) + lc * 8;
            else if (t == 2) src = Vh + (size_t)r * SS + lc * 8;
            else             src = Vl + (size_t)r * SS + lc * 8;
            CP_ASYNC16(dst, src);
        }
        CP_COMMIT();
    };

    load_kv(0, 0);

    CP_WAIT1();
    __syncthreads();
    uint32_t qfh[4][4], qfl[4][4];
#pragma unroll
    for (int ks = 0; ks < 4; ks++) {
        uint32_t off = (uint32_t)(wid * 16 + a_row) * AT_PITCH + (ks * 16 + a_kof) * 2;
        ldsm_x4(qfh[ks][0], qfh[ks][1], qfh[ks][2], qfh[ks][3], sbase + AT_STAGE + off);
        ldsm_x4(qfl[ks][0], qfl[ks][1], qfl[ks][2], qfl[ks][3], sbase + AT_STAGE + 18432 + off);
    }
    __syncthreads();

    float O[8][4];
#pragma unroll
    for (int j = 0; j < 8; j++)
#pragma unroll
        for (int r = 0; r < 4; r++) O[j][r] = 0.f;
    float m0 = -1e30f, m1 = -1e30f, l0 = 0.f, l1 = 0.f;

    for (int kt = 0; kt < SS / 64; kt++) {
        const int s = kt & 1;
        if (kt + 1 < SS / 64) { load_kv(s ^ 1, kt + 1); CP_WAIT1(); }
        else                  { CP_WAIT0(); }
        __syncthreads();

        const uint32_t sKh = sbase + s * AT_STAGE;
        const uint32_t sKl = sKh + AT_TILE;
        const uint32_t sVh = sKh + 2 * AT_TILE;
        const uint32_t sVl = sKh + 3 * AT_TILE;

        float sa[8][4];
#pragma unroll
        for (int j = 0; j < 8; j++)
#pragma unroll
            for (int r = 0; r < 4; r++) sa[j][r] = 0.f;
#pragma unroll
        for (int ks = 0; ks < 4; ks++) {
            const uint32_t ko = (uint32_t)(ks * 16 + b_kof) * 2;
            uint32_t kb4[4][4];
#pragma unroll
            for (int p = 0; p < 4; p++)
                ldsm_x4(kb4[p][0], kb4[p][1], kb4[p][2], kb4[p][3],
                        sKh + (uint32_t)(p * 16 + b_nof) * AT_PITCH + ko);
#pragma unroll
            for (int j = 0; j < 8; j++) {
                const int p = j >> 1, hh = j & 1;
                mma16816(sa[j][0], sa[j][1], sa[j][2], sa[j][3],
                         qfh[ks][0], qfh[ks][1], qfh[ks][2], qfh[ks][3],
                         kb4[p][hh * 2], kb4[p][hh * 2 + 1]);
                mma16816(sa[j][0], sa[j][1], sa[j][2], sa[j][3],
                         qfl[ks][0], qfl[ks][1], qfl[ks][2], qfl[ks][3],
                         kb4[p][hh * 2], kb4[p][hh * 2 + 1]);
            }
#pragma unroll
            for (int p = 0; p < 4; p++)
                ldsm_x4(kb4[p][0], kb4[p][1], kb4[p][2], kb4[p][3],
                        sKl + (uint32_t)(p * 16 + b_nof) * AT_PITCH + ko);
#pragma unroll
            for (int j = 0; j < 8; j++) {
                const int p = j >> 1, hh = j & 1;
                mma16816(sa[j][0], sa[j][1], sa[j][2], sa[j][3],
                         qfh[ks][0], qfh[ks][1], qfh[ks][2], qfh[ks][3],
                         kb4[p][hh * 2], kb4[p][hh * 2 + 1]);
            }
        }

        // ---- online softmax
        float tm0 = -1e30f, tm1 = -1e30f;
#pragma unroll
        for (int j = 0; j < 8; j++) {
            tm0 = fmaxf(tm0, fmaxf(sa[j][0], sa[j][1]));
            tm1 = fmaxf(tm1, fmaxf(sa[j][2], sa[j][3]));
        }
        tm0 = fmaxf(tm0, __shfl_xor_sync(0xffffffffu, tm0, 1));
        tm0 = fmaxf(tm0, __shfl_xor_sync(0xffffffffu, tm0, 2));
        tm1 = fmaxf(tm1, __shfl_xor_sync(0xffffffffu, tm1, 1));
        tm1 = fmaxf(tm1, __shfl_xor_sync(0xffffffffu, tm1, 2));
        float mn0 = fmaxf(m0, tm0), mn1 = fmaxf(m1, tm1);
        float al0 = __expf(m0 - mn0), al1 = __expf(m1 - mn1);
        m0 = mn0; m1 = mn1;
        float ls0 = 0.f, ls1 = 0.f;
#pragma unroll
        for (int j = 0; j < 8; j++) {
            sa[j][0] = __expf(sa[j][0] - m0);
            sa[j][1] = __expf(sa[j][1] - m0);
            sa[j][2] = __expf(sa[j][2] - m1);
            sa[j][3] = __expf(sa[j][3] - m1);
            ls0 += sa[j][0] + sa[j][1];
            ls1 += sa[j][2] + sa[j][3];
        }
        ls0 += __shfl_xor_sync(0xffffffffu, ls0, 1);
        ls0 += __shfl_xor_sync(0xffffffffu, ls0, 2);
        ls1 += __shfl_xor_sync(0xffffffffu, ls1, 1);
        ls1 += __shfl_xor_sync(0xffffffffu, ls1, 2);
        l0 = l0 * al0 + ls0;
        l1 = l1 * al1 + ls1;
#pragma unroll
        for (int j = 0; j < 8; j++) {
            O[j][0] *= al0; O[j][1] *= al0;
            O[j][2] *= al1; O[j][3] *= al1;
        }

        // ---- pack P hi/lo
        uint32_t pah[4][4], pal[4][4];
#pragma unroll
        for (int t = 0; t < 4; t++) {
            float e[8] = {sa[2*t][0], sa[2*t][1], sa[2*t][2], sa[2*t][3],
                          sa[2*t+1][0], sa[2*t+1][1], sa[2*t+1][2], sa[2*t+1][3]};
            float hi[8], lo[8];
#pragma unroll
            for (int u = 0; u < 8; u++) {
                hi[u] = __bfloat162float(__float2bfloat16(e[u]));
                lo[u] = e[u] - hi[u];
            }
            pah[t][0] = pack_bf162(hi[0], hi[1]);
            pah[t][1] = pack_bf162(hi[2], hi[3]);
            pah[t][2] = pack_bf162(hi[4], hi[5]);
            pah[t][3] = pack_bf162(hi[6], hi[7]);
            pal[t][0] = pack_bf162(lo[0], lo[1]);
            pal[t][1] = pack_bf162(lo[2], lo[3]);
            pal[t][2] = pack_bf162(lo[4], lo[5]);
            pal[t][3] = pack_bf162(lo[6], lo[7]);
        }

        // ---- O += Ph*Vh + Pl*Vh + Ph*Vl
#pragma unroll
        for (int t = 0; t < 4; t++) {
            const uint32_t ko = (uint32_t)(t * 16 + b_kof) * 2;
            uint32_t vb4[4][4];
#pragma unroll
            for (int p = 0; p < 4; p++)
                ldsm_x4(vb4[p][0], vb4[p][1], vb4[p][2], vb4[p][3],
                        sVh + (uint32_t)(p * 16 + b_nof) * AT_PITCH + ko);
#pragma unroll
            for (int j = 0; j < 8; j++) {
                const int p = j >> 1, hh = j & 1;
                mma16816(O[j][0], O[j][1], O[j][2], O[j][3],
                         pah[t][0], pah[t][1], pah[t][2], pah[t][3],
                         vb4[p][hh * 2], vb4[p][hh * 2 + 1]);
                mma16816(O[j][0], O[j][1], O[j][2], O[j][3],
                         pal[t][0], pal[t][1], pal[t][2], pal[t][3],
                         vb4[p][hh * 2], vb4[p][hh * 2 + 1]);
            }
#pragma unroll
            for (int p = 0; p < 4; p++)
                ldsm_x4(vb4[p][0], vb4[p][1], vb4[p][2], vb4[p][3],
                        sVl + (uint32_t)(p * 16 + b_nof) * AT_PITCH + ko);
#pragma unroll
            for (int j = 0; j < 8; j++) {
                const int p = j >> 1, hh = j & 1;
                mma16816(O[j][0], O[j][1], O[j][2], O[j][3],
                         pah[t][0], pah[t][1], pah[t][2], pah[t][3],
                         vb4[p][hh * 2], vb4[p][hh * 2 + 1]);
            }
        }
        __syncthreads();
    }

    // ---- epilogue: normalize, gate (from fused buffer), write bf16 hi/lo
    float inv0 = 1.f / l0, inv1 = 1.f / l1;
    int r0 = qt * 128 + wid * 16 + (lane >> 2);
    int r1 = r0 + 8;
    const int coff = h * DD + ((lane & 3) << 1);
    size_t gb0 = (size_t)(b * SS + r0) * NQKVG + COL_G + coff;
    size_t gb1 = (size_t)(b * SS + r1) * NQKVG + COL_G + coff;
    size_t ab0 = (size_t)(b * SS + r0) * (NH * DD) + coff;
    size_t ab1 = (size_t)(b * SS + r1) * (NH * DD) + coff;
#pragma unroll
    for (int j = 0; j < 8; j++) {
        float2 gA = *(const float2*)(d_qkvg + gb0 + j * 8);
        float2 gB = *(const float2*)(d_qkvg + gb1 + j * 8);
        float vAx = O[j][0] * inv0 * (1.f / (1.f + __expf(-gA.x)));
        float vAy = O[j][1] * inv0 * (1.f / (1.f + __expf(-gA.y)));
        float vBx = O[j][2] * inv1 * (1.f / (1.f + __expf(-gB.x)));
        float vBy = O[j][3] * inv1 * (1.f / (1.f + __expf(-gB.y)));
        __nv_bfloat16 hAx = __float2bfloat16(vAx), hAy = __float2bfloat16(vAy);
        __nv_bfloat16 hBx = __float2bfloat16(vBx), hBy = __float2bfloat16(vBy);
        *(__nv_bfloat162*)(g_ab_h + ab0 + j * 8) = __nv_bfloat162(hAx, hAy);
        *(__nv_bfloat162*)(g_ab_h + ab1 + j * 8) = __nv_bfloat162(hBx, hBy);
        *(__nv_bfloat162*)(g_ab_l + ab0 + j * 8) = __nv_bfloat162(
            __float2bfloat16(vAx - __bfloat162float(hAx)),
            __float2bfloat16(vAy - __bfloat162float(hAy)));
        *(__nv_bfloat162*)(g_ab_l + ab1 + j * 8) = __nv_bfloat162(
            __float2bfloat16(vBx - __bfloat162float(hBx)),
            __float2bfloat16(vBy - __bfloat162float(hBy)));
    }
}

// ---------------- launch -----------------------------------------------------
extern "C" void kernel_launch(void* const* d_in, const int* in_sizes, int n_in,
                              void* d_out, int out_size)
{
    const float* hs   = (const float*)d_in[0];
    const float* cosb = (const float*)d_in[1];
    const float* sinb = (const float*)d_in[2];
    const float* Wq   = (const float*)d_in[3];
    const float* Wk   = (const float*)d_in[4];
    const float* Wv   = (const float*)d_in[5];
    const float* Wg   = (const float*)d_in[6];
    const float* Wo   = (const float*)d_in[7];
    const float* qg   = (const float*)d_in[8];
    const float* kg   = (const float*)d_in[9];
    float* out = (float*)d_out;

    float* qkvg;
    cudaGetSymbolAddress((void**)&qkvg, d_qkvg);

    __nv_bfloat16 *hs_h, *hs_l, *wqkvg_h, *wqkvg_l, *wo_h, *wo_l, *ab_h, *ab_l;
    __nv_bfloat16 *qh, *ql, *kh, *kl, *vth, *vtl;
    cudaGetSymbolAddress((void**)&hs_h, g_hs_h);
    cudaGetSymbolAddress((void**)&hs_l, g_hs_l);
    cudaGetSymbolAddress((void**)&wqkvg_h, g_wqkvg_h);
    cudaGetSymbolAddress((void**)&wqkvg_l, g_wqkvg_l);
    cudaGetSymbolAddress((void**)&wo_h, g_wo_h);
    cudaGetSymbolAddress((void**)&wo_l, g_wo_l);
    cudaGetSymbolAddress((void**)&ab_h, g_ab_h);
    cudaGetSymbolAddress((void**)&ab_l, g_ab_l);
    cudaGetSymbolAddress((void**)&qh,  g_qh);
    cudaGetSymbolAddress((void**)&ql,  g_ql);
    cudaGetSymbolAddress((void**)&kh,  g_kh);
    cudaGetSymbolAddress((void**)&kl,  g_kl);
    cudaGetSymbolAddress((void**)&vth, g_vth);
    cudaGetSymbolAddress((void**)&vtl, g_vtl);

    cudaFuncSetAttribute(gemm_bf16x3, cudaFuncAttributeMaxDynamicSharedMemorySize, GEMM_SMEM);
    cudaFuncSetAttribute(attn_hmma, cudaFuncAttributeMaxDynamicSharedMemorySize, ATT_SMEM);

    // splits: hs, and the four weights packed into one [4608 x 2048] matrix
    {
        int n4;
        n4 = MROWS * HID / 4;
        split_bf16<<<(n4 + 255) / 256, 256>>>(hs, hs_h, hs_l, n4);
        n4 = HID * HID / 4;   // Wq rows [0,2048)
        split_bf16<<<(n4 + 255) / 256, 256>>>(Wq, wqkvg_h, wqkvg_l, n4);
        n4 = NKV * DD * HID / 4;  // Wk rows [2048,2304)
        split_bf16<<<(n4 + 255) / 256, 256>>>(
            Wk, wqkvg_h + (size_t)COL_K * HID, wqkvg_l + (size_t)COL_K * HID, n4);
        n4 = NKV * DD * HID / 4;  // Wv rows [2304,2560)
        split_bf16<<<(n4 + 255) / 256, 256>>>(
            Wv, wqkvg_h + (size_t)COL_V * HID, wqkvg_l + (size_t)COL_V * HID, n4);
        n4 = HID * HID / 4;   // Wg rows [2560,4608)
        split_bf16<<<(n4 + 255) / 256, 256>>>(
            Wg, wqkvg_h + (size_t)COL_G * HID, wqkvg_l + (size_t)COL_G * HID, n4);
        n4 = HID * HID / 4;
        split_bf16<<<(n4 + 255) / 256, 256>>>(Wo, wo_h, wo_l, n4);
    }

    // fused Q|K|V|G projection via HMMA (one launch, N=4608)
    gemm_bf16x3<<<dim3(NQKVG / 128, MROWS / 128), 256, GEMM_SMEM>>>(
        hs_h, hs_l, wqkvg_h, wqkvg_l, qkvg, MROWS, NQKVG, HID);

    // RMSNorm + RoPE + hi/lo split (Q scaled), V transpose+split
    {
        int rows_q = MROWS * NH;
        int rows_k = MROWS * NKV;
        norm_rope_split<<<(rows_q * 32 + 255) / 256, 256>>>(
            qkvg, cosb, sinb, qg, qh, ql, NH, rows_q, QSCALE, NQKVG, COL_Q);
        norm_rope_split<<<(rows_k * 32 + 255) / 256, 256>>>(
            qkvg, cosb, sinb, kg, kh, kl, NKV, rows_k, 1.0f, NQKVG, COL_K);
        split_v_trans<<<dim3(SS / 64, NKV, BB), 256>>>(qkvg, vth, vtl);
    }

    // attention (+ fused sigmoid gate, writes ab hi/lo directly)
    attn_hmma<<<dim3(SS / 128, NH, BB), 256, ATT_SMEM>>>();

    // output projection
    gemm_bf16x3<<<dim3(HID / 128, MROWS / 128), 256, GEMM_SMEM>>>(
        ab_h, ab_l, wo_h, wo_l, out, MROWS, HID, HID);
}

// round 16
// speedup vs baseline: 1.0545x; 1.0545x over previous
#include <cuda_runtime.h>
#include <cuda_bf16.h>
#include <math.h>
#include <cstdint>

// Problem constants
#define BB 2
#define SS 2048
#define HID 2048
#define NH 32
#define NKV 4
#define DD 64
#define N_REP 8
#define MROWS (BB * SS)           // 4096
#define QSCALE 0.125f             // D^-0.5
#define EPS 1e-6f

// fused projection layout: [Wq(2048) ; Wk(256) ; Wv(256) ; Wg(2048)]
#define NQKVG 4608
#define COL_Q 0
#define COL_K 2048
#define COL_V 2304
#define COL_G 2560

// ---------------- async copy helpers ----------------------------------------
#define CP_ASYNC16(smem_u32a, gptr) \
    asm volatile("cp.async.cg.shared.global [%0], [%1], 16;" :: "r"(smem_u32a), "l"(gptr))
#define CP_COMMIT() asm volatile("cp.async.commit_group;" ::: "memory")
#define CP_WAIT2()  asm volatile("cp.async.wait_group 2;" ::: "memory")
#define CP_WAIT1()  asm volatile("cp.async.wait_group 1;" ::: "memory")
#define CP_WAIT0()  asm volatile("cp.async.wait_group 0;" ::: "memory")

__device__ __forceinline__ uint32_t smem_u32(const void* p) {
    uint32_t a;
    asm("{ .reg .u64 t; cvta.to.shared.u64 t, %1; cvt.u32.u64 %0, t; }" : "=r"(a) : "l"(p));
    return a;
}
__device__ __forceinline__ void ldsm_x4(uint32_t& r0, uint32_t& r1, uint32_t& r2, uint32_t& r3,
                                        uint32_t addr) {
    asm volatile("ldmatrix.sync.aligned.m8n8.x4.shared.b16 {%0,%1,%2,%3}, [%4];"
                 : "=r"(r0), "=r"(r1), "=r"(r2), "=r"(r3) : "r"(addr));
}
__device__ __forceinline__ void mma16816(float& c0, float& c1, float& c2, float& c3,
                                         uint32_t a0, uint32_t a1, uint32_t a2, uint32_t a3,
                                         uint32_t b0, uint32_t b1) {
    asm volatile(
        "mma.sync.aligned.m16n8k16.row.col.f32.bf16.bf16.f32 "
        "{%0,%1,%2,%3}, {%4,%5,%6,%7}, {%8,%9}, {%0,%1,%2,%3};"
        : "+f"(c0), "+f"(c1), "+f"(c2), "+f"(c3)
        : "r"(a0), "r"(a1), "r"(a2), "r"(a3), "r"(b0), "r"(b1));
}
__device__ __forceinline__ uint32_t pack_bf162(float x, float y) {
    __nv_bfloat162 h = __floats2bfloat162_rn(x, y);
    return *reinterpret_cast<uint32_t*>(&h);
}

// ---------------- scratch (static device memory) ----------------------------
__device__ float d_qkvg[(size_t)MROWS * NQKVG];   // fused projection output

__device__ __nv_bfloat16 g_hs_h[(size_t)MROWS * HID];
__device__ __nv_bfloat16 g_hs_l[(size_t)MROWS * HID];
__device__ __nv_bfloat16 g_wqkvg_h[(size_t)NQKVG * HID];
__device__ __nv_bfloat16 g_wqkvg_l[(size_t)NQKVG * HID];
__device__ __nv_bfloat16 g_wo_h[(size_t)HID * HID];
__device__ __nv_bfloat16 g_wo_l[(size_t)HID * HID];
__device__ __nv_bfloat16 g_ab_h[(size_t)MROWS * HID];
__device__ __nv_bfloat16 g_ab_l[(size_t)MROWS * HID];

// pre-split attention operands (bf16 hi/lo)
__device__ __nv_bfloat16 g_qh[(size_t)MROWS * NH * DD];
__device__ __nv_bfloat16 g_ql[(size_t)MROWS * NH * DD];
__device__ __nv_bfloat16 g_kh[(size_t)MROWS * NKV * DD];
__device__ __nv_bfloat16 g_kl[(size_t)MROWS * NKV * DD];
__device__ __nv_bfloat16 g_vth[(size_t)MROWS * NKV * DD];  // [b][kvh][d][s]
__device__ __nv_bfloat16 g_vtl[(size_t)MROWS * NKV * DD];

// ---------------- split fp32 -> bf16 hi/lo ----------------------------------
__global__ __launch_bounds__(256) void split_bf16(
    const float* __restrict__ X, __nv_bfloat16* __restrict__ hi,
    __nv_bfloat16* __restrict__ lo, int n4)
{
    int i = blockIdx.x * 256 + threadIdx.x;
    if (i >= n4) return;
    float4 x = ((const float4*)X)[i];
    __nv_bfloat16 h0 = __float2bfloat16(x.x);
    __nv_bfloat16 h1 = __float2bfloat16(x.y);
    __nv_bfloat16 h2 = __float2bfloat16(x.z);
    __nv_bfloat16 h3 = __float2bfloat16(x.w);
    __nv_bfloat16 l0 = __float2bfloat16(x.x - __bfloat162float(h0));
    __nv_bfloat16 l1 = __float2bfloat16(x.y - __bfloat162float(h1));
    __nv_bfloat16 l2 = __float2bfloat16(x.z - __bfloat162float(h2));
    __nv_bfloat16 l3 = __float2bfloat16(x.w - __bfloat162float(h3));
    ((__nv_bfloat162*)hi)[2*i]     = __nv_bfloat162(h0, h1);
    ((__nv_bfloat162*)hi)[2*i + 1] = __nv_bfloat162(h2, h3);
    ((__nv_bfloat162*)lo)[2*i]     = __nv_bfloat162(l0, l1);
    ((__nv_bfloat162*)lo)[2*i + 1] = __nv_bfloat162(l2, l3);
}

// ---------------- HMMA bf16x3 GEMM: single K pass, 3-stage pipeline ----------
// C[m,n] = sum_k (AhBh + AhBl + AlBh). CTA 128x128, BK=64, 8 warps 32x64.
#define GPAD 72
#define G_TILE (128 * GPAD * 2)     // 18432 per tile
#define G_STAGE4 (4 * G_TILE)       // 73728 per stage
#define GEMM_SMEM (3 * G_STAGE4)    // 221184, 3-stage

__global__ __launch_bounds__(256) void gemm_bf16x3(
    const __nv_bfloat16* __restrict__ Ah, const __nv_bfloat16* __restrict__ Al,
    const __nv_bfloat16* __restrict__ Bh, const __nv_bfloat16* __restrict__ Bl,
    float* __restrict__ C, int M, int N, int K)
{
    extern __shared__ char smem[];
    const uint32_t sbase = smem_u32(smem);
    const int tid = threadIdx.x;
    const int wid = tid >> 5;
    const int lane = tid & 31;
    const int wm = wid & 3;
    const int wn = wid >> 2;
    const int bm = blockIdx.y * 128;
    const int bn = blockIdx.x * 128;

    const int nchunk = K >> 6;
    const int lrow = tid >> 3;
    const int lcol = (tid & 7) * 8;

    const int g = lane >> 3, li = lane & 7;
    const int a_row = (g & 1) * 8 + li;
    const int a_kof = (g >> 1) * 8;
    const int b_nof = (g >> 1) * 8 + li;
    const int b_kof = (g & 1) * 8;

    float acc[2][8][4];
#pragma unroll
    for (int mt = 0; mt < 2; mt++)
#pragma unroll
        for (int nt = 0; nt < 8; nt++)
#pragma unroll
            for (int r = 0; r < 4; r++) acc[mt][nt][r] = 0.f;

    auto load_stage = [&](int s, int k0) {
        const uint32_t st = sbase + s * G_STAGE4;
#pragma unroll
        for (int u = 0; u < 4; u++) {
            int row = lrow + u * 32;
            uint32_t so = (uint32_t)(row * GPAD + lcol) * 2;
            const size_t ga = (size_t)(bm + row) * K + k0 + lcol;
            const size_t gb = (size_t)(bn + row) * K + k0 + lcol;
            CP_ASYNC16(st + so,              Ah + ga);
            CP_ASYNC16(st + G_TILE + so,     Al + ga);
            CP_ASYNC16(st + 2 * G_TILE + so, Bh + gb);
            CP_ASYNC16(st + 3 * G_TILE + so, Bl + gb);
        }
        CP_COMMIT();
    };

    load_stage(0, 0);
    if (nchunk > 1) load_stage(1, 64);

    for (int i = 0; i < nchunk; i++) {
        const int s = i % 3;
        if (i + 2 < nchunk)      { load_stage((i + 2) % 3, (i + 2) << 6); CP_WAIT2(); }
        else if (i + 1 < nchunk) { CP_WAIT1(); }
        else                     { CP_WAIT0(); }
        __syncthreads();

        const uint32_t st = sbase + s * G_STAGE4;
        const uint32_t aBase = st + (uint32_t)((wm * 32 + a_row) * GPAD + a_kof) * 2;
        const uint32_t bBase = st + 2 * G_TILE + (uint32_t)((wn * 64 + b_nof) * GPAD + b_kof) * 2;

#pragma unroll
        for (int ks = 0; ks < 4; ks++) {
            const uint32_t ko = ks * 32;
            uint32_t ah0[4], ah1[4], al0[4], al1[4];
            ldsm_x4(ah0[0], ah0[1], ah0[2], ah0[3], aBase + ko);
            ldsm_x4(ah1[0], ah1[1], ah1[2], ah1[3], aBase + (uint32_t)(16 * GPAD) * 2 + ko);
            ldsm_x4(al0[0], al0[1], al0[2], al0[3], aBase + G_TILE + ko);
            ldsm_x4(al1[0], al1[1], al1[2], al1[3], aBase + G_TILE + (uint32_t)(16 * GPAD) * 2 + ko);

            uint32_t bf[4][4];
#pragma unroll
            for (int p = 0; p < 4; p++)
                ldsm_x4(bf[p][0], bf[p][1], bf[p][2], bf[p][3],
                        bBase + (uint32_t)(p * 16 * GPAD) * 2 + ko);
#pragma unroll
            for (int nt = 0; nt < 8; nt++) {
                const int p = nt >> 1, h = nt & 1;
                uint32_t b0 = bf[p][h * 2], b1 = bf[p][h * 2 + 1];
                mma16816(acc[0][nt][0], acc[0][nt][1], acc[0][nt][2], acc[0][nt][3],
                         ah0[0], ah0[1], ah0[2], ah0[3], b0, b1);
                mma16816(acc[1][nt][0], acc[1][nt][1], acc[1][nt][2], acc[1][nt][3],
                         ah1[0], ah1[1], ah1[2], ah1[3], b0, b1);
                mma16816(acc[0][nt][0], acc[0][nt][1], acc[0][nt][2], acc[0][nt][3],
                         al0[0], al0[1], al0[2], al0[3], b0, b1);
                mma16816(acc[1][nt][0], acc[1][nt][1], acc[1][nt][2], acc[1][nt][3],
                         al1[0], al1[1], al1[2], al1[3], b0, b1);
            }
#pragma unroll
            for (int p = 0; p < 4; p++)
                ldsm_x4(bf[p][0], bf[p][1], bf[p][2], bf[p][3],
                        bBase + G_TILE + (uint32_t)(p * 16 * GPAD) * 2 + ko);
#pragma unroll
            for (int nt = 0; nt < 8; nt++) {
                const int p = nt >> 1, h = nt & 1;
                uint32_t b0 = bf[p][h * 2], b1 = bf[p][h * 2 + 1];
                mma16816(acc[0][nt][0], acc[0][nt][1], acc[0][nt][2], acc[0][nt][3],
                         ah0[0], ah0[1], ah0[2], ah0[3], b0, b1);
                mma16816(acc[1][nt][0], acc[1][nt][1], acc[1][nt][2], acc[1][nt][3],
                         ah1[0], ah1[1], ah1[2], ah1[3], b0, b1);
            }
        }
        __syncthreads();
    }

    const int crow = lane >> 2;
    const int ccol = (lane & 3) * 2;
#pragma unroll
    for (int mt = 0; mt < 2; mt++) {
        int m0 = bm + wm * 32 + mt * 16 + crow;
#pragma unroll
        for (int nt = 0; nt < 8; nt++) {
            int n0 = bn + wn * 64 + nt * 8 + ccol;
            *(float2*)(C + (size_t)m0 * N + n0)       = make_float2(acc[mt][nt][0], acc[mt][nt][1]);
            *(float2*)(C + (size_t)(m0 + 8) * N + n0) = make_float2(acc[mt][nt][2], acc[mt][nt][3]);
        }
    }
}

// ---------------- RMSNorm + RoPE + bf16 hi/lo split (strided input) ----------
__global__ __launch_bounds__(256) void norm_rope_split(
    const float* __restrict__ X, const float* __restrict__ cosb,
    const float* __restrict__ sinb, const float* __restrict__ gamma,
    __nv_bfloat16* __restrict__ Xh, __nv_bfloat16* __restrict__ Xl,
    int nheads, int total_rows, float scale, int rowstride, int colbase)
{
    int warp = (blockIdx.x * 256 + threadIdx.x) >> 5;
    int lane = threadIdx.x & 31;
    if (warp >= total_rows) return;
    int bs = warp / nheads;
    int h  = warp - bs * nheads;
    const float* x = X + (size_t)bs * rowstride + colbase + h * DD;
    float v0 = x[lane];
    float v1 = x[lane + 32];
    float ss = v0 * v0 + v1 * v1;
#pragma unroll
    for (int o = 16; o > 0; o >>= 1) ss += __shfl_xor_sync(0xffffffffu, ss, o);
    float inv = rsqrtf(ss * (1.0f / DD) + EPS);
    float n0 = v0 * inv * gamma[lane];
    float n1 = v1 * inv * gamma[lane + 32];
    const float* cp = cosb + (size_t)bs * DD;
    const float* sp = sinb + (size_t)bs * DD;
    float r0 = (n0 * cp[lane]      - n1 * sp[lane])      * scale;
    float r1 = (n1 * cp[lane + 32] + n0 * sp[lane + 32]) * scale;
    __nv_bfloat16 h0 = __float2bfloat16(r0);
    __nv_bfloat16 h1 = __float2bfloat16(r1);
    Xh[(size_t)warp * DD + lane]      = h0;
    Xh[(size_t)warp * DD + lane + 32] = h1;
    Xl[(size_t)warp * DD + lane]      = __float2bfloat16(r0 - __bfloat162float(h0));
    Xl[(size_t)warp * DD + lane + 32] = __float2bfloat16(r1 - __bfloat162float(h1));
}

// ---------------- V: fp32 strided -> bf16 hi/lo transposed [b,kvh,d,s] -------
__global__ __launch_bounds__(256) void split_v_trans(
    const float* __restrict__ QKVG, __nv_bfloat16* __restrict__ Vth,
    __nv_bfloat16* __restrict__ Vtl)
{
    __shared__ float tile[64][65];
    const int sb = blockIdx.x * 64;
    const int kvh = blockIdx.y;
    const int b = blockIdx.z;
    const int tid = threadIdx.x;
#pragma unroll
    for (int i = tid; i < 1024; i += 256) {
        int r = i >> 4;
        int c4 = (i & 15) << 2;
        float4 v = *(const float4*)(QKVG + (size_t)(b * SS + sb + r) * NQKVG + COL_V + kvh * DD + c4);
        tile[r][c4 + 0] = v.x; tile[r][c4 + 1] = v.y;
        tile[r][c4 + 2] = v.z; tile[r][c4 + 3] = v.w;
    }
    __syncthreads();
#pragma unroll
    for (int i = tid; i < 1024; i += 256) {
        int d = i >> 4;
        int s4 = (i & 15) << 2;
        size_t base = ((size_t)(b * NKV + kvh) * DD + d) * SS + sb + s4;
        __nv_bfloat16 hs4[4], ls4[4];
#pragma unroll
        for (int j = 0; j < 4; j++) {
            float v = tile[s4 + j][d];
            hs4[j] = __float2bfloat16(v);
            ls4[j] = __float2bfloat16(v - __bfloat162float(hs4[j]));
        }
        *(__nv_bfloat162*)(Vth + base)     = __nv_bfloat162(hs4[0], hs4[1]);
        *(__nv_bfloat162*)(Vth + base + 2) = __nv_bfloat162(hs4[2], hs4[3]);
        *(__nv_bfloat162*)(Vtl + base)     = __nv_bfloat162(ls4[0], ls4[1]);
        *(__nv_bfloat162*)(Vtl + base + 2) = __nv_bfloat162(ls4[2], ls4[3]);
    }
}

// ---------------- HMMA flash attention: M=64, 128-thread CTAs, 3 CTAs/SM -----
// Same per-warp work shape as before (16 rows/warp, 4 warps). KV stages
// identical; Q staging is 64 rows. Higher SMSP occupancy to hide softmax.
#define AT_PITCH 144
#define AT_TILE (64 * AT_PITCH)       // 9216
#define AT_STAGE (4 * AT_TILE)        // 36864
#define ATT_SMEM (2 * AT_STAGE)       // 73728

__global__ __launch_bounds__(128, 3) void attn_hmma()
{
    extern __shared__ char sm8[];
    const uint32_t sbase = smem_u32(sm8);
    const int qt = blockIdx.x;          // 64-row q tile
    const int h  = blockIdx.y;
    const int b  = blockIdx.z;
    const int kvh = h >> 3;
    const int tid = threadIdx.x;        // 0..127
    const int wid = tid >> 5;           // 0..3
    const int lane = tid & 31;
    const int g = lane >> 3, li = lane & 7;
    const int a_row = (g & 1) * 8 + li;
    const int a_kof = (g >> 1) * 8;
    const int b_nof = (g >> 1) * 8 + li;
    const int b_kof = (g & 1) * 8;
    const int lr = tid >> 3;            // 0..15
    const int lc = tid & 7;

    // ---- group A: Q hi/lo (64 rows) into stage-1 area
    {
        const __nv_bfloat16* Qh = g_qh + ((size_t)(b * SS + qt * 64) * NH + h) * DD;
        const __nv_bfloat16* Ql = g_ql + ((size_t)(b * SS + qt * 64) * NH + h) * DD;
#pragma unroll
        for (int u = 0; u < 4; u++) {
            int r = u * 16 + lr;
            uint32_t dof = (uint32_t)r * AT_PITCH + lc * 16;
            CP_ASYNC16(sbase + AT_STAGE + dof,         Qh + (size_t)r * (NH * DD) + lc * 8);
            CP_ASYNC16(sbase + AT_STAGE + 9216 + dof,  Ql + (size_t)r * (NH * DD) + lc * 8);
        }
        CP_COMMIT();
    }

    auto load_kv = [&](int s, int kt) {
        const __nv_bfloat16* Kh = g_kh + ((size_t)(b * SS + kt * 64) * NKV + kvh) * DD;
        const __nv_bfloat16* Kl = g_kl + ((size_t)(b * SS + kt * 64) * NKV + kvh) * DD;
        const __nv_bfloat16* Vh = g_vth + (size_t)(b * NKV + kvh) * DD * SS + kt * 64;
        const __nv_bfloat16* Vl = g_vtl + (size_t)(b * NKV + kvh) * DD * SS + kt * 64;
        const uint32_t sb0 = sbase + s * AT_STAGE;
#pragma unroll
        for (int u = 0; u < 16; u++) {
            const int t = u >> 2;               // tile 0..3
            const int r = (u & 3) * 16 + lr;    // row 0..63
            uint32_t dst = sb0 + t * AT_TILE + (uint32_t)r * AT_PITCH + lc * 16;
            const __nv_bfloat16* src;
            if      (t == 0) src = Kh + (size_t)r * (NKV * DD) + lc * 8;
            else if (t == 1) src = Kl + (size_t)r * (NKV * DD) + lc * 8;
            else if (t == 2) src = Vh + (size_t)r * SS + lc * 8;
            else             src = Vl + (size_t)r * SS + lc * 8;
            CP_ASYNC16(dst, src);
        }
        CP_COMMIT();
    };

    load_kv(0, 0);

    CP_WAIT1();
    __syncthreads();
    uint32_t qfh[4][4], qfl[4][4];
#pragma unroll
    for (int ks = 0; ks < 4; ks++) {
        uint32_t off = (uint32_t)(wid * 16 + a_row) * AT_PITCH + (ks * 16 + a_kof) * 2;
        ldsm_x4(qfh[ks][0], qfh[ks][1], qfh[ks][2], qfh[ks][3], sbase + AT_STAGE + off);
        ldsm_x4(qfl[ks][0], qfl[ks][1], qfl[ks][2], qfl[ks][3], sbase + AT_STAGE + 9216 + off);
    }
    __syncthreads();

    float O[8][4];
#pragma unroll
    for (int j = 0; j < 8; j++)
#pragma unroll
        for (int r = 0; r < 4; r++) O[j][r] = 0.f;
    float m0 = -1e30f, m1 = -1e30f, l0 = 0.f, l1 = 0.f;

    for (int kt = 0; kt < SS / 64; kt++) {
        const int s = kt & 1;
        if (kt + 1 < SS / 64) { load_kv(s ^ 1, kt + 1); CP_WAIT1(); }
        else                  { CP_WAIT0(); }
        __syncthreads();

        const uint32_t sKh = sbase + s * AT_STAGE;
        const uint32_t sKl = sKh + AT_TILE;
        const uint32_t sVh = sKh + 2 * AT_TILE;
        const uint32_t sVl = sKh + 3 * AT_TILE;

        float sa[8][4];
#pragma unroll
        for (int j = 0; j < 8; j++)
#pragma unroll
            for (int r = 0; r < 4; r++) sa[j][r] = 0.f;
#pragma unroll
        for (int ks = 0; ks < 4; ks++) {
            const uint32_t ko = (uint32_t)(ks * 16 + b_kof) * 2;
            uint32_t kb4[4][4];
#pragma unroll
            for (int p = 0; p < 4; p++)
                ldsm_x4(kb4[p][0], kb4[p][1], kb4[p][2], kb4[p][3],
                        sKh + (uint32_t)(p * 16 + b_nof) * AT_PITCH + ko);
#pragma unroll
            for (int j = 0; j < 8; j++) {
                const int p = j >> 1, hh = j & 1;
                mma16816(sa[j][0], sa[j][1], sa[j][2], sa[j][3],
                         qfh[ks][0], qfh[ks][1], qfh[ks][2], qfh[ks][3],
                         kb4[p][hh * 2], kb4[p][hh * 2 + 1]);
                mma16816(sa[j][0], sa[j][1], sa[j][2], sa[j][3],
                         qfl[ks][0], qfl[ks][1], qfl[ks][2], qfl[ks][3],
                         kb4[p][hh * 2], kb4[p][hh * 2 + 1]);
            }
#pragma unroll
            for (int p = 0; p < 4; p++)
                ldsm_x4(kb4[p][0], kb4[p][1], kb4[p][2], kb4[p][3],
                        sKl + (uint32_t)(p * 16 + b_nof) * AT_PITCH + ko);
#pragma unroll
            for (int j = 0; j < 8; j++) {
                const int p = j >> 1, hh = j & 1;
                mma16816(sa[j][0], sa[j][1], sa[j][2], sa[j][3],
                         qfh[ks][0], qfh[ks][1], qfh[ks][2], qfh[ks][3],
                         kb4[p][hh * 2], kb4[p][hh * 2 + 1]);
            }
        }

        // ---- online softmax
        float tm0 = -1e30f, tm1 = -1e30f;
#pragma unroll
        for (int j = 0; j < 8; j++) {
            tm0 = fmaxf(tm0, fmaxf(sa[j][0], sa[j][1]));
            tm1 = fmaxf(tm1, fmaxf(sa[j][2], sa[j][3]));
        }
        tm0 = fmaxf(tm0, __shfl_xor_sync(0xffffffffu, tm0, 1));
        tm0 = fmaxf(tm0, __shfl_xor_sync(0xffffffffu, tm0, 2));
        tm1 = fmaxf(tm1, __shfl_xor_sync(0xffffffffu, tm1, 1));
        tm1 = fmaxf(tm1, __shfl_xor_sync(0xffffffffu, tm1, 2));
        float mn0 = fmaxf(m0, tm0), mn1 = fmaxf(m1, tm1);
        float al0 = __expf(m0 - mn0), al1 = __expf(m1 - mn1);
        m0 = mn0; m1 = mn1;
        float ls0 = 0.f, ls1 = 0.f;
#pragma unroll
        for (int j = 0; j < 8; j++) {
            sa[j][0] = __expf(sa[j][0] - m0);
            sa[j][1] = __expf(sa[j][1] - m0);
            sa[j][2] = __expf(sa[j][2] - m1);
            sa[j][3] = __expf(sa[j][3] - m1);
            ls0 += sa[j][0] + sa[j][1];
            ls1 += sa[j][2] + sa[j][3];
        }
        ls0 += __shfl_xor_sync(0xffffffffu, ls0, 1);
        ls0 += __shfl_xor_sync(0xffffffffu, ls0, 2);
        ls1 += __shfl_xor_sync(0xffffffffu, ls1, 1);
        ls1 += __shfl_xor_sync(0xffffffffu, ls1, 2);
        l0 = l0 * al0 + ls0;
        l1 = l1 * al1 + ls1;
#pragma unroll
        for (int j = 0; j < 8; j++) {
            O[j][0] *= al0; O[j][1] *= al0;
            O[j][2] *= al1; O[j][3] *= al1;
        }

        // ---- pack P hi/lo
        uint32_t pah[4][4], pal[4][4];
#pragma unroll
        for (int t = 0; t < 4; t++) {
            float e[8] = {sa[2*t][0], sa[2*t][1], sa[2*t][2], sa[2*t][3],
                          sa[2*t+1][0], sa[2*t+1][1], sa[2*t+1][2], sa[2*t+1][3]};
            float hi[8], lo[8];
#pragma unroll
            for (int u = 0; u < 8; u++) {
                hi[u] = __bfloat162float(__float2bfloat16(e[u]));
                lo[u] = e[u] - hi[u];
            }
            pah[t][0] = pack_bf162(hi[0], hi[1]);
            pah[t][1] = pack_bf162(hi[2], hi[3]);
            pah[t][2] = pack_bf162(hi[4], hi[5]);
            pah[t][3] = pack_bf162(hi[6], hi[7]);
            pal[t][0] = pack_bf162(lo[0], lo[1]);
            pal[t][1] = pack_bf162(lo[2], lo[3]);
            pal[t][2] = pack_bf162(lo[4], lo[5]);
            pal[t][3] = pack_bf162(lo[6], lo[7]);
        }

        // ---- O += Ph*Vh + Pl*Vh + Ph*Vl
#pragma unroll
        for (int t = 0; t < 4; t++) {
            const uint32_t ko = (uint32_t)(t * 16 + b_kof) * 2;
            uint32_t vb4[4][4];
#pragma unroll
            for (int p = 0; p < 4; p++)
                ldsm_x4(vb4[p][0], vb4[p][1], vb4[p][2], vb4[p][3],
                        sVh + (uint32_t)(p * 16 + b_nof) * AT_PITCH + ko);
#pragma unroll
            for (int j = 0; j < 8; j++) {
                const int p = j >> 1, hh = j & 1;
                mma16816(O[j][0], O[j][1], O[j][2], O[j][3],
                         pah[t][0], pah[t][1], pah[t][2], pah[t][3],
                         vb4[p][hh * 2], vb4[p][hh * 2 + 1]);
                mma16816(O[j][0], O[j][1], O[j][2], O[j][3],
                         pal[t][0], pal[t][1], pal[t][2], pal[t][3],
                         vb4[p][hh * 2], vb4[p][hh * 2 + 1]);
            }
#pragma unroll
            for (int p = 0; p < 4; p++)
                ldsm_x4(vb4[p][0], vb4[p][1], vb4[p][2], vb4[p][3],
                        sVl + (uint32_t)(p * 16 + b_nof) * AT_PITCH + ko);
#pragma unroll
            for (int j = 0; j < 8; j++) {
                const int p = j >> 1, hh = j & 1;
                mma16816(O[j][0], O[j][1], O[j][2], O[j][3],
                         pah[t][0], pah[t][1], pah[t][2], pah[t][3],
                         vb4[p][hh * 2], vb4[p][hh * 2 + 1]);
            }
        }
        __syncthreads();
    }

    // ---- epilogue: normalize, gate (from fused buffer), write bf16 hi/lo
    float inv0 = 1.f / l0, inv1 = 1.f / l1;
    int r0 = qt * 64 + wid * 16 + (lane >> 2);
    int r1 = r0 + 8;
    const int coff = h * DD + ((lane & 3) << 1);
    size_t gb0 = (size_t)(b * SS + r0) * NQKVG + COL_G + coff;
    size_t gb1 = (size_t)(b * SS + r1) * NQKVG + COL_G + coff;
    size_t ab0 = (size_t)(b * SS + r0) * (NH * DD) + coff;
    size_t ab1 = (size_t)(b * SS + r1) * (NH * DD) + coff;
#pragma unroll
    for (int j = 0; j < 8; j++) {
        float2 gA = *(const float2*)(d_qkvg + gb0 + j * 8);
        float2 gB = *(const float2*)(d_qkvg + gb1 + j * 8);
        float vAx = O[j][0] * inv0 * (1.f / (1.f + __expf(-gA.x)));
        float vAy = O[j][1] * inv0 * (1.f / (1.f + __expf(-gA.y)));
        float vBx = O[j][2] * inv1 * (1.f / (1.f + __expf(-gB.x)));
        float vBy = O[j][3] * inv1 * (1.f / (1.f + __expf(-gB.y)));
        __nv_bfloat16 hAx = __float2bfloat16(vAx), hAy = __float2bfloat16(vAy);
        __nv_bfloat16 hBx = __float2bfloat16(vBx), hBy = __float2bfloat16(vBy);
        *(__nv_bfloat162*)(g_ab_h + ab0 + j * 8) = __nv_bfloat162(hAx, hAy);
        *(__nv_bfloat162*)(g_ab_h + ab1 + j * 8) = __nv_bfloat162(hBx, hBy);
        *(__nv_bfloat162*)(g_ab_l + ab0 + j * 8) = __nv_bfloat162(
            __float2bfloat16(vAx - __bfloat162float(hAx)),
            __float2bfloat16(vAy - __bfloat162float(hAy)));
        *(__nv_bfloat162*)(g_ab_l + ab1 + j * 8) = __nv_bfloat162(
            __float2bfloat16(vBx - __bfloat162float(hBx)),
            __float2bfloat16(vBy - __bfloat162float(hBy)));
    }
}

// ---------------- launch -----------------------------------------------------
extern "C" void kernel_launch(void* const* d_in, const int* in_sizes, int n_in,
                              void* d_out, int out_size)
{
    const float* hs   = (const float*)d_in[0];
    const float* cosb = (const float*)d_in[1];
    const float* sinb = (const float*)d_in[2];
    const float* Wq   = (const float*)d_in[3];
    const float* Wk   = (const float*)d_in[4];
    const float* Wv   = (const float*)d_in[5];
    const float* Wg   = (const float*)d_in[6];
    const float* Wo   = (const float*)d_in[7];
    const float* qg   = (const float*)d_in[8];
    const float* kg   = (const float*)d_in[9];
    float* out = (float*)d_out;

    float* qkvg;
    cudaGetSymbolAddress((void**)&qkvg, d_qkvg);

    __nv_bfloat16 *hs_h, *hs_l, *wqkvg_h, *wqkvg_l, *wo_h, *wo_l, *ab_h, *ab_l;
    __nv_bfloat16 *qh, *ql, *kh, *kl, *vth, *vtl;
    cudaGetSymbolAddress((void**)&hs_h, g_hs_h);
    cudaGetSymbolAddress((void**)&hs_l, g_hs_l);
    cudaGetSymbolAddress((void**)&wqkvg_h, g_wqkvg_h);
    cudaGetSymbolAddress((void**)&wqkvg_l, g_wqkvg_l);
    cudaGetSymbolAddress((void**)&wo_h, g_wo_h);
    cudaGetSymbolAddress((void**)&wo_l, g_wo_l);
    cudaGetSymbolAddress((void**)&ab_h, g_ab_h);
    cudaGetSymbolAddress((void**)&ab_l, g_ab_l);
    cudaGetSymbolAddress((void**)&qh,  g_qh);
    cudaGetSymbolAddress((void**)&ql,  g_ql);
    cudaGetSymbolAddress((void**)&kh,  g_kh);
    cudaGetSymbolAddress((void**)&kl,  g_kl);
    cudaGetSymbolAddress((void**)&vth, g_vth);
    cudaGetSymbolAddress((void**)&vtl, g_vtl);

    cudaFuncSetAttribute(gemm_bf16x3, cudaFuncAttributeMaxDynamicSharedMemorySize, GEMM_SMEM);
    cudaFuncSetAttribute(attn_hmma, cudaFuncAttributeMaxDynamicSharedMemorySize, ATT_SMEM);

    // splits: hs, and the four weights packed into one [4608 x 2048] matrix
    {
        int n4;
        n4 = MROWS * HID / 4;
        split_bf16<<<(n4 + 255) / 256, 256>>>(hs, hs_h, hs_l, n4);
        n4 = HID * HID / 4;   // Wq rows [0,2048)
        split_bf16<<<(n4 + 255) / 256, 256>>>(Wq, wqkvg_h, wqkvg_l, n4);
        n4 = NKV * DD * HID / 4;  // Wk rows [2048,2304)
        split_bf16<<<(n4 + 255) / 256, 256>>>(
            Wk, wqkvg_h + (size_t)COL_K * HID, wqkvg_l + (size_t)COL_K * HID, n4);
        n4 = NKV * DD * HID / 4;  // Wv rows [2304,2560)
        split_bf16<<<(n4 + 255) / 256, 256>>>(
            Wv, wqkvg_h + (size_t)COL_V * HID, wqkvg_l + (size_t)COL_V * HID, n4);
        n4 = HID * HID / 4;   // Wg rows [2560,4608)
        split_bf16<<<(n4 + 255) / 256, 256>>>(
            Wg, wqkvg_h + (size_t)COL_G * HID, wqkvg_l + (size_t)COL_G * HID, n4);
        n4 = HID * HID / 4;
        split_bf16<<<(n4 + 255) / 256, 256>>>(Wo, wo_h, wo_l, n4);
    }

    // fused Q|K|V|G projection via HMMA (one launch, N=4608)
    gemm_bf16x3<<<dim3(NQKVG / 128, MROWS / 128), 256, GEMM_SMEM>>>(
        hs_h, hs_l, wqkvg_h, wqkvg_l, qkvg, MROWS, NQKVG, HID);

    // RMSNorm + RoPE + hi/lo split (Q scaled), V transpose+split
    {
        int rows_q = MROWS * NH;
        int rows_k = MROWS * NKV;
        norm_rope_split<<<(rows_q * 32 + 255) / 256, 256>>>(
            qkvg, cosb, sinb, qg, qh, ql, NH, rows_q, QSCALE, NQKVG, COL_Q);
        norm_rope_split<<<(rows_k * 32 + 255) / 256, 256>>>(
            qkvg, cosb, sinb, kg, kh, kl, NKV, rows_k, 1.0f, NQKVG, COL_K);
        split_v_trans<<<dim3(SS / 64, NKV, BB), 256>>>(qkvg, vth, vtl);
    }

    // attention (+ fused sigmoid gate): M=64 tiles, 128 threads, 3 CTAs/SM
    attn_hmma<<<dim3(SS / 64, NH, BB), 128, ATT_SMEM>>>();

    // output projection
    gemm_bf16x3<<<dim3(HID / 128, MROWS / 128), 256, GEMM_SMEM>>>(
        ab_h, ab_l, wo_h, wo_l, out, MROWS, HID, HID);
}